// round 3
// baseline (speedup 1.0000x reference)
#include <cuda_runtime.h>
#include <cstdint>
#include <math_constants.h>

#define TT 1024
#define BB 128
#define LL 128

__device__ float g_res[BB];
__device__ int   g_ctr = 0;

// named barrier over the 256 scan threads (numerator warp excluded)
#define BARS() asm volatile("bar.sync 1, 256;" ::: "memory")

#define FMA2(d, a, b, c) \
    asm("fma.rn.f32x2 %0, %1, %2, %3;" : "=l"(d) : "l"(a), "l"(b), "l"(c))
#define ADD2(d, a, b) \
    asm("add.rn.f32x2 %0, %1, %2;" : "=l"(d) : "l"(a), "l"(b))

__device__ __forceinline__ int mval(const uint8_t* m, int t, int b, bool is8) {
    size_t idx = (size_t)t * BB + b;
    return is8 ? (m[idx] != 0) : (((const int*)m)[idx] != 0);
}

// u buffer: 64 floats, 4 pad, 64 floats -> hi-half chunks hit disjoint banks
__device__ __forceinline__ int uidx(int j) { return j + ((j >> 6) << 2); }

// ============================================================
// Block b = batch b. 288 threads:
//   tid 0..255 : scan. warp w (0..7), lane; half = lane>>4, jlo = lane&15,
//                output j = w*16 + jlo, i-range = [64*half, 64*half+64).
//                Partner lane^16 has same j, other half -> shfl.xor 16 combine.
//   tid 256..287 : length (ballot search) + numerator, concurrent.
// ============================================================
__global__ void __launch_bounds__(288, 1)
crf_fused(const float* __restrict__ pred, const int* __restrict__ tgt,
          const uint8_t* __restrict__ mask, const float* __restrict__ trans,
          const float* __restrict__ start, const float* __restrict__ endsc,
          float* __restrict__ out) {
    int b   = blockIdx.x;
    int tid = threadIdx.x;

    __shared__ __align__(16) float ub[2][LL + 4];
    __shared__ float red[8];
    __shared__ float smaxs[8];
    __shared__ float s_den, s_num;
    __shared__ int s_len, s_last;

    unsigned long long E2[32];   // 64 E values packed as f32x2
    float ctm = 0.f;

    if (tid < 256) {
        int lane = tid & 31, w = tid >> 5;
        int half = lane >> 4, jlo = lane & 15;
        int j = w * 16 + jlo;
        int ibase = half * 64;

        // ---- prologue: E half-column + full column max ----
        float hm = -CUDART_INF_F;
        #pragma unroll
        for (int i = 0; i < 64; i++)
            hm = fmaxf(hm, __ldg(trans + (ibase + i) * LL + j));
        ctm = fmaxf(hm, __shfl_xor_sync(0xffffffffu, hm, 16));
        #pragma unroll
        for (int m = 0; m < 32; m++) {
            float lo = __expf(__ldg(trans + (ibase + 2 * m)     * LL + j) - ctm);
            float hi = __expf(__ldg(trans + (ibase + 2 * m + 1) * LL + j) - ctm);
            unsigned long long pk;
            asm("mov.b64 %0, {%1, %2};" : "=l"(pk) : "f"(lo), "f"(hi));
            E2[m] = pk;
        }
    } else {
        // ---- length via 2-round ballot search on monotone mask column ----
        int lane = tid - 256;
        bool is8 = (mask[1] != 0);
        unsigned b1 = __ballot_sync(0xffffffffu, mval(mask, lane * 32, b, is8));
        int base = (31 - __clz(b1)) * 32;
        unsigned b2 = __ballot_sync(0xffffffffu, mval(mask, base + lane, b, is8));
        if (lane == 0) s_len = base + __popc(b2);
    }
    __syncthreads();
    int len = s_len;

    if (tid < 256) {
        int lane = tid & 31, w = tid >> 5;
        int half = lane >> 4, jlo = lane & 15;
        int j = w * 16 + jlo;
        const float* ubase = ub[0] + half * 68;   // lo: 0, hi: 68 (bank-shifted)
        const float* ubas1 = ub[1] + half * 68;

        // ---- init: alpha0 = start + pred[0], exact one-time normalize ----
        float g0 = __ldg(start + j) + __ldg(pred + (size_t)b * LL + j);
        float m = g0;
        #pragma unroll
        for (int o = 16; o; o >>= 1) m = fmaxf(m, __shfl_xor_sync(0xffffffffu, m, o));
        if (lane == 0) red[w] = m;
        BARS();
        float m0 = red[0];
        #pragma unroll
        for (int k = 1; k < 8; k++) m0 = fmaxf(m0, red[k]);
        double C = (double)m0;
        if (half == 0) ub[0][uidx(j)] = __expf(g0 - m0);

        // ---- pred prefetch (depth 3) + mult pipeline (depth 1) ----
        const float* pj = pred + (size_t)b * LL + j;
        int t1 = (1 < len) ? 1 : 0;
        int t2 = (2 < len) ? 2 : len - 1;
        int t3 = (3 < len) ? 3 : len - 1;
        float prB = __ldg(pj + (size_t)t1 * BB * LL);
        float prC = __ldg(pj + (size_t)t2 * BB * LL);
        float prD = __ldg(pj + (size_t)t3 * BB * LL);
        float mcur = __expf(prB + ctm);   // mult for t=1
        prB = prC; prC = prD;
        BARS();

        int p = 0;
        for (int t = 1; t < len; t++) {
            int tf = (t + 3 < len) ? (t + 3) : (len - 1);
            float prN = __ldg(pj + (size_t)tf * BB * LL);
            float mnext = __expf(prB + ctm);          // mult for t+1 (hidden)

            // deferred renorm fold (concurrent with LDS/FMA below)
            float rinv = 1.f;
            bool fold = ((t & 3) == 2) && (t > 2);
            if (fold) {
                float mx = smaxs[0];
                #pragma unroll
                for (int k = 1; k < 8; k++) mx = fmaxf(mx, smaxs[k]);
                rinv = __frcp_rn(mx);
                C += (double)__logf(mx);
            }

            // half-matvec: partial[j] = sum_{i in half} u[i] * E[i][j]
            const ulonglong2* u2 = (const ulonglong2*)(p ? ubas1 : ubase);
            unsigned long long a0 = 0ull, a1 = 0ull, a2 = 0ull, a3 = 0ull;
            #pragma unroll
            for (int c = 0; c < 16; c += 2) {
                ulonglong2 x = u2[c];
                ulonglong2 y = u2[c + 1];
                FMA2(a0, E2[2 * c + 0], x.x, a0);
                FMA2(a1, E2[2 * c + 1], x.y, a1);
                FMA2(a2, E2[2 * c + 2], y.x, a2);
                FMA2(a3, E2[2 * c + 3], y.y, a3);
            }
            ADD2(a0, a0, a2);
            ADD2(a1, a1, a3);
            ADD2(a0, a0, a1);
            float lo, hi;
            asm("mov.b64 {%0,%1}, %2;" : "=f"(lo), "=f"(hi) : "l"(a0));
            float part = lo + hi;

            // combine the two i-halves (partner lane = lane^16)
            float sum = part + __shfl_xor_sync(0xffffffffu, part, 16);
            float v = sum * mcur;
            if (fold) v *= rinv;

            if (half == 0) ub[p ^ 1][uidx(j)] = v;
            if ((t & 3) == 0) {                       // measure (off critical path)
                unsigned mm = __reduce_max_sync(0xffffffffu, __float_as_uint(v));
                if (lane == 0) smaxs[w] = __uint_as_float(mm);
            }
            prB = prC; prC = prN; mcur = mnext;
            p ^= 1;
            BARS();
        }

        // ---- denominator ----
        float z = 0.f;
        if (half == 0) z = ub[p][uidx(j)] * __expf(__ldg(endsc + j));
        #pragma unroll
        for (int o = 16; o; o >>= 1) z += __shfl_xor_sync(0xffffffffu, z, o);
        if (lane == 0) red[w] = z;
        BARS();
        if (tid == 0) {
            float ssum = 0.f;
            #pragma unroll
            for (int k = 0; k < 8; k++) ssum += red[k];
            s_den = (float)(C + (double)logf(ssum));
        }
    } else {
        // ---- numerator (concurrent with the scan) ----
        int lane = tid - 256;
        float part = 0.f;
        #pragma unroll 4
        for (int k = 0; k < 32; k++) {
            int t = k * 32 + lane;
            if (t == 0) {
                int y0 = __ldg(tgt + b);
                part += __ldg(start + y0) + __ldg(pred + (size_t)b * LL + y0);
            } else if (t < len) {
                int y  = __ldg(tgt + t * BB + b);
                int yp = __ldg(tgt + (t - 1) * BB + b);
                part += __ldg(trans + yp * LL + y) + __ldg(pred + ((size_t)t * BB + b) * LL + y);
            }
        }
        #pragma unroll
        for (int o = 16; o; o >>= 1) part += __shfl_xor_sync(0xffffffffu, part, o);
        if (lane == 0) {
            int yl = __ldg(tgt + (len - 1) * BB + b);
            s_num = part + __ldg(endsc + yl);
        }
    }
    __syncthreads();

    if (tid == 0) {
        g_res[b] = s_den - s_num;
        __threadfence();
        int c = atomicAdd(&g_ctr, 1);
        s_last = (c == (int)gridDim.x - 1) ? 1 : 0;
    }
    __syncthreads();

    if (s_last && tid < 32) {
        float v = __ldcg(&g_res[tid])      + __ldcg(&g_res[tid + 32])
                + __ldcg(&g_res[tid + 64]) + __ldcg(&g_res[tid + 96]);
        #pragma unroll
        for (int o = 16; o; o >>= 1) v += __shfl_xor_sync(0xffffffffu, v, o);
        if (tid == 0) { out[0] = v * (1.0f / BB); g_ctr = 0; }
    }
}

// ============================================================
extern "C" void kernel_launch(void* const* d_in, const int* in_sizes, int n_in,
                              void* d_out, int out_size) {
    const float*   pred  = (const float*)d_in[0];
    const int*     tgt   = (const int*)d_in[1];
    const uint8_t* mask  = (const uint8_t*)d_in[2];
    const float*   trans = (const float*)d_in[3];
    const float*   start = (const float*)d_in[4];
    const float*   endsc = (const float*)d_in[5];

    crf_fused<<<BB, 288>>>(pred, tgt, mask, trans, start, endsc, (float*)d_out);
}